// round 14
// baseline (speedup 1.0000x reference)
#include <cuda_runtime.h>
#include <cstdint>

#define DEVI __device__ __forceinline__

constexpr int NQ = 131072;   // queries
constexpr int MN = 8192;     // tree nodes
constexpr float F_EPS = 1e-6f;
constexpr float F_BIG = 1e9f;

// ---------------- shared-memory layout (float word offsets) ------------------
constexpr int OFF_W1 = 0;        // [2][100]                       (200)
constexpr int OFF_B1 = 200;      // 100 -> 300, pad 304
constexpr int OFF_W2 = 304;      // [100][104] = 10400 -> 10704 (cols 100..103 zero)
constexpr int OFF_B2 = 10704;    // 104 -> 10808
constexpr int OFF_W3 = 10808;    // [100][32] = 3200 -> 14008 (cols 30,31 zero)
constexpr int OFF_B3 = 14008;    // 32 -> 14040
constexpr int OFF_W4 = 14040;    // [32][2] = 64 -> 14104
constexpr int OFF_B4 = 14104;    // 2 pad 8 -> 14112
constexpr int OFF_H  = 14112;    // per-group h block: [k][4 rows]
constexpr int H_GSTRIDE = 404;   // 400 + 4 pad
constexpr int R_ROWS  = 4;       // rows per 8-lane group
constexpr int GROUPS  = 60;      // 8-lane groups per CTA (4 per warp)
constexpr int MLP_BLOCK = 480;   // 15 warps, reg cap 136 (R12: used 104)
constexpr int MLP_GRID  = 152;
constexpr int SMEM_FLOATS = OFF_H + GROUPS * H_GSTRIDE;   // 38352
constexpr int SMEM_BYTES  = SMEM_FLOATS * 4;              // 153,408 B

constexpr int CHUNKS = (MN + NQ) / R_ROWS;            // 34816 (exact)
constexpr int SLOTS  = MLP_GRID * GROUPS;             // 9120
constexpr int ROUNDS = (CHUNKS + SLOTS - 1) / SLOTS;  // 4 -> 95.4% fill

// traverse kernel: whole g_emb staged in smem (R13 version, measured win)
constexpr int TRAV_BLOCK = 1024;
constexpr int TRAV_GRID  = NQ / TRAV_BLOCK;           // 128, one query/thread
constexpr int TRAV_SMEM  = (MN + 8) * 8;              // 65,600 B

// ---------------- scratch (device globals: no allocation allowed) ------------
__device__ float2 g_emb[MN + 8]; // +8 pad: node 1023's child loads reach 8192..
__device__ float2 g_qx[NQ];      // transformed queries
__device__ float4 g_node2[MN];   // (prob2.x, prob2.y, has_child, 0)

typedef unsigned long long u64;

// ---------------- packed fp32x2 helpers (sm_100+ PTX) ------------------------
DEVI u64 pack2(float lo, float hi) {
    u64 r;
    asm("mov.b64 %0, {%1, %2};"
        : "=l"(r) : "r"(__float_as_uint(lo)), "r"(__float_as_uint(hi)));
    return r;
}
DEVI void unpack2(u64 v, float &lo, float &hi) {
    unsigned a, b;
    asm("mov.b64 {%0, %1}, %2;" : "=r"(a), "=r"(b) : "l"(v));
    lo = __uint_as_float(a); hi = __uint_as_float(b);
}
DEVI void fma2(u64 &d, u64 a, u64 b) {
    asm("fma.rn.f32x2 %0, %1, %2, %0;" : "+l"(d) : "l"(a), "l"(b));
}

// torch.nn.PairwiseDistance: ||a - b + eps||_2
DEVI float pdist(float ax, float ay, float bx, float by) {
    float dx = ax - bx + F_EPS;
    float dy = ay - by + F_EPS;
    return sqrtf(fmaf(dx, dx, dy * dy));
}

// ---------------- kernel 1: fused node+query MLP (R12 body, measured best) ---
// Work unit = 4-row chunk per 8-lane group (4 groups/warp). Lane q owns layer-2
// cols {2q+16j, 2q+16j+1 : j=0..5} (LDS.64 pairs) + singleton col 96+q, for
// all 4 rows. h exchanged via the group's SMEM block ([k][4 rows], one LDS.128
// per k). Layer 3: cols {2q,2q+1,2q+16,2q+17}. Layer 4 reduced via shfl.xor.
__global__ void __launch_bounds__(MLP_BLOCK, 1)
mlp_all_kernel(const float* __restrict__ x, const float* __restrict__ nd,
               const float* __restrict__ W1, const float* __restrict__ b1,
               const float* __restrict__ W2, const float* __restrict__ b2,
               const float* __restrict__ W3, const float* __restrict__ b3,
               const float* __restrict__ W4, const float* __restrict__ b4) {
    extern __shared__ float sm[];
    const int t = threadIdx.x;

    // zero weight region (covers all pad slots), then fill
    for (int i = t; i < OFF_H; i += MLP_BLOCK) sm[i] = 0.f;
    __syncthreads();
    for (int i = t; i < 200; i += MLP_BLOCK) sm[OFF_W1 + i] = W1[i];
    for (int i = t; i < 100; i += MLP_BLOCK) sm[OFF_B1 + i] = b1[i];
    for (int i = t; i < 10000; i += MLP_BLOCK) {
        int k = i / 100, j = i - k * 100;
        sm[OFF_W2 + k * 104 + j] = W2[i];
    }
    for (int j = t; j < 100; j += MLP_BLOCK) sm[OFF_B2 + j] = b2[j];
    for (int i = t; i < 3000; i += MLP_BLOCK) {
        int k = i / 30, j = i - k * 30;
        sm[OFF_W3 + k * 32 + j] = W3[i];
    }
    for (int i = t; i < 30; i += MLP_BLOCK) sm[OFF_B3 + i] = b3[i];
    for (int i = t; i < 60; i += MLP_BLOCK) sm[OFF_W4 + i] = W4[i];
    if (t < 2) sm[OFF_B4 + t] = b4[t];
    __syncthreads();

    const int lane = t & 31;
    const int q   = lane & 7;                   // lane within group
    const int gid = (t >> 5) * 4 + (lane >> 3); // group in CTA, 0..59
    float* hg = sm + OFF_H + gid * H_GSTRIDE;

    int chunk = blockIdx.x * GROUPS + gid;

    for (int rnd = 0; rnd < ROUNDS; rnd++, chunk += SLOTS) {
        const bool active = chunk < CHUNKS;
        const int row0 = chunk * R_ROWS;

        // ---- layer 1 (2 -> 100): lane computes h1[kk][0..3], kk = q+8j -----
        if (active) {
            const bool isnode = row0 < MN;   // MN%4==0: chunk never straddles
            const float4* src = (const float4*)(
                (isnode ? nd : x) + (size_t)(isnode ? row0 : row0 - MN) * 2);
            float4 v0 = __ldg(src + 0), v1 = __ldg(src + 1);
            // rows: (v0.x,v0.y) (v0.z,v0.w) (v1.x,v1.y) (v1.z,v1.w)
            float x0[4] = {v0.x, v0.z, v1.x, v1.z};
            float x1[4] = {v0.y, v0.w, v1.y, v1.w};
            #pragma unroll
            for (int j = 0; j < 13; j++) {
                int kk = q + 8 * j;
                if (kk < 100) {
                    float wa = sm[OFF_W1 + kk];
                    float wb = sm[OFF_W1 + 100 + kk];
                    float bb = sm[OFF_B1 + kk];
                    float hv[4];
                    #pragma unroll
                    for (int r = 0; r < 4; r++)
                        hv[r] = fmaxf(fmaf(x0[r], wa, fmaf(x1[r], wb, bb)), 0.f);
                    *(float4*)(hg + kk * 4) = make_float4(hv[0], hv[1], hv[2], hv[3]);
                }
            }
        }
        __syncwarp();

        // ---- layer 2 (100 -> 100): 6 col-pairs + 1 singleton, x 4 rows -----
        u64 acc[6][4];
        float sc[4];
        {
            #pragma unroll
            for (int j = 0; j < 6; j++) {
                u64 bv = *(const u64*)(sm + OFF_B2 + 2 * q + 16 * j);
                #pragma unroll
                for (int r = 0; r < 4; r++) acc[j][r] = bv;
            }
            float bs = sm[OFF_B2 + 96 + q];
            #pragma unroll
            for (int r = 0; r < 4; r++) sc[r] = bs;
        }
        const float* w2q = sm + OFF_W2 + 2 * q;
        const float* w2s = sm + OFF_W2 + 96 + q;
        #pragma unroll 4
        for (int k = 0; k < 100; k++) {
            float4 h4 = *(const float4*)(hg + k * 4);
            float hr[4] = {h4.x, h4.y, h4.z, h4.w};
            u64 hh[4];
            #pragma unroll
            for (int r = 0; r < 4; r++) hh[r] = pack2(hr[r], hr[r]);
            const float* wr = w2q + k * 104;
            #pragma unroll
            for (int j = 0; j < 6; j++) {
                u64 w = *(const u64*)(wr + 16 * j);
                #pragma unroll
                for (int r = 0; r < 4; r++) fma2(acc[j][r], hh[r], w);
            }
            float wsv = w2s[k * 104];
            #pragma unroll
            for (int r = 0; r < 4; r++) sc[r] = fmaf(hr[r], wsv, sc[r]);
        }
        __syncwarp();   // all lanes done reading h1 before overwriting with h2

        // relu + write h2 back to the group's h block
        if (active) {
            #pragma unroll
            for (int j = 0; j < 6; j++) {
                float va[4], vb[4];
                #pragma unroll
                for (int r = 0; r < 4; r++) {
                    float a, b; unpack2(acc[j][r], a, b);
                    va[r] = fmaxf(a, 0.f); vb[r] = fmaxf(b, 0.f);
                }
                int c0 = 2 * q + 16 * j;
                *(float4*)(hg + c0 * 4)       = make_float4(va[0], va[1], va[2], va[3]);
                *(float4*)(hg + (c0 + 1) * 4) = make_float4(vb[0], vb[1], vb[2], vb[3]);
            }
            if (q < 4) {   // singleton cols 96..99
                float vs[4];
                #pragma unroll
                for (int r = 0; r < 4; r++) vs[r] = fmaxf(sc[r], 0.f);
                *(float4*)(hg + (96 + q) * 4) = make_float4(vs[0], vs[1], vs[2], vs[3]);
            }
        }
        __syncwarp();

        // ---- layer 3 (100 -> 30 pad 32): lane cols {2q,2q+1,2q+16,2q+17} ---
        u64 a3[2][4];
        {
            u64 b0 = *(const u64*)(sm + OFF_B3 + 2 * q);
            u64 b1v = *(const u64*)(sm + OFF_B3 + 2 * q + 16);
            #pragma unroll
            for (int r = 0; r < 4; r++) { a3[0][r] = b0; a3[1][r] = b1v; }
        }
        const float* w3q = sm + OFF_W3 + 2 * q;
        #pragma unroll 4
        for (int k = 0; k < 100; k++) {
            float4 h4 = *(const float4*)(hg + k * 4);
            float hr[4] = {h4.x, h4.y, h4.z, h4.w};
            u64 hh[4];
            #pragma unroll
            for (int r = 0; r < 4; r++) hh[r] = pack2(hr[r], hr[r]);
            const float* wr = w3q + k * 32;
            u64 w0 = *(const u64*)(wr);
            u64 w1v = *(const u64*)(wr + 16);
            #pragma unroll
            for (int r = 0; r < 4; r++) {
                fma2(a3[0][r], hh[r], w0);
                fma2(a3[1][r], hh[r], w1v);
            }
        }

        // ---- layer 4 (30 -> 2): partials over this lane's 4 cols -----------
        float o0[4], o1[4];
        #pragma unroll
        for (int r = 0; r < 4; r++) { o0[r] = 0.f; o1[r] = 0.f; }
        #pragma unroll
        for (int jj = 0; jj < 2; jj++) {
            int cA = 2 * q + 16 * jj;
            float2 wA = *(const float2*)(sm + OFF_W4 + 2 * cA);
            float2 wB = *(const float2*)(sm + OFF_W4 + 2 * cA + 2);
            #pragma unroll
            for (int r = 0; r < 4; r++) {
                float a, b; unpack2(a3[jj][r], a, b);
                a = fmaxf(a, 0.f); b = fmaxf(b, 0.f);
                o0[r] = fmaf(a, wA.x, o0[r]);
                o1[r] = fmaf(a, wA.y, o1[r]);
                o0[r] = fmaf(b, wB.x, o0[r]);
                o1[r] = fmaf(b, wB.y, o1[r]);
            }
        }
        // reduce across the 8-lane group (full-warp shfl, all threads join)
        #pragma unroll
        for (int r = 0; r < 4; r++) {
            o0[r] += __shfl_xor_sync(0xffffffffu, o0[r], 1);
            o0[r] += __shfl_xor_sync(0xffffffffu, o0[r], 2);
            o0[r] += __shfl_xor_sync(0xffffffffu, o0[r], 4);
            o1[r] += __shfl_xor_sync(0xffffffffu, o1[r], 1);
            o1[r] += __shfl_xor_sync(0xffffffffu, o1[r], 2);
            o1[r] += __shfl_xor_sync(0xffffffffu, o1[r], 4);
        }
        if (active && q < 4) {
            // lane q emits row q (static selects, no local-mem indexing)
            float s0 = (q == 0) ? o0[0] : (q == 1) ? o0[1] : (q == 2) ? o0[2] : o0[3];
            float s1 = (q == 0) ? o1[0] : (q == 1) ? o1[1] : (q == 2) ? o1[2] : o1[3];
            float2 ov = make_float2(s0 + sm[OFF_B4 + 0], s1 + sm[OFF_B4 + 1]);
            int row = row0 + q;
            if (row < MN) g_emb[row] = ov;
            else          g_qx[row - MN] = ov;
        }
        __syncwarp();
    }
}

// ---------------- kernel 2: per-node prob2 / has_child (query-independent) ---
__global__ void precompute_kernel(const float* __restrict__ node_classes,
                                  const int* __restrict__ children) {
    int i = blockIdx.x * blockDim.x + threadIdx.x;
    if (i >= MN) return;
    const int4* ch4 = (const int4*)children;
    int4 c0 = ch4[2 * i], c1 = ch4[2 * i + 1];
    int ci[8] = {c0.x, c0.y, c0.z, c0.w, c1.x, c1.y, c1.z, c1.w};
    float2 e = g_emb[i];
    float d[8]; bool any = false;
    #pragma unroll
    for (int k = 0; k < 8; k++) {
        int c = ci[k];
        if (c >= 0) {
            float2 ec = g_emb[c];
            d[k] = pdist(e.x, e.y, ec.x, ec.y);   // dist(emb[cur], c_emb)
            any = true;
        } else d[k] = F_BIG;
    }
    float4 r = make_float4(0.f, 0.f, 0.f, 0.f);
    if (any) {
        float mn = d[0];
        #pragma unroll
        for (int k = 1; k < 8; k++) mn = fminf(mn, d[k]);
        float S = 0.f, m0 = 0.f, m1 = 0.f;
        #pragma unroll
        for (int k = 0; k < 8; k++) {
            float ek = expf(-(d[k] - mn));
            S += ek;
            int c = ci[k];
            if (c >= 0) {
                m0 = fmaf(ek, node_classes[2 * c + 0], m0);
                m1 = fmaf(ek, node_classes[2 * c + 1], m1);
            }
        }
        m0 /= S; m1 /= S;
        r.x = logf(fmaxf(m0, 1e-30f));
        r.y = logf(fmaxf(m1, 1e-30f));
        r.z = 1.f;
    }
    g_node2[i] = r;
}

// ---------------- kernel 3: tree traversal (g_emb staged in smem, R13 win) ---
// Complete 8-ary tree: children of node i are {8i+1..8i+8} clipped at 8191;
// leaves are i >= 1024. All child loads hit the CTA's smem copy of g_emb
// (65.6 KB) -> 29-cyc LDS instead of LDG, shortening the dependent chain.
__global__ void __launch_bounds__(TRAV_BLOCK)
traverse_kernel(float* __restrict__ out) {
    extern __shared__ float2 semb[];
    // stage g_emb (MN+8 float2 = 4100 float4, 1024 threads -> ~4 each)
    {
        const float4* srcv = (const float4*)g_emb;
        float4* dstv = (float4*)semb;
        for (int i = threadIdx.x; i < (MN + 8) / 2; i += TRAV_BLOCK)
            dstv[i] = __ldg(srcv + i);
    }
    __syncthreads();

    const int qi = blockIdx.x * TRAV_BLOCK + threadIdx.x;   // covers NQ exactly
    const float2 qx = g_qx[qi];
    const float q0 = qx.x, q1 = qx.y;

    int cur = 0;
    float2 e0 = semb[0];
    float d0 = pdist(e0.x, e0.y, q0, q1);
    float prob = 0.f, o0 = 0.f, o1 = 0.f;

    for (int t = 0; t < 16; t++) {
        const int base = 8 * cur + 1;
        float d[8];
        if (cur < 1024) {
            #pragma unroll
            for (int k = 0; k < 8; k++) {
                float2 ec = semb[base + k];    // padded: base+7 <= 8192 < MN+8
                d[k] = pdist(ec.x, ec.y, q0, q1);
            }
            if (cur == 1023) d[7] = F_BIG;     // node 8192 doesn't exist
        } else {
            #pragma unroll
            for (int k = 0; k < 8; k++) d[k] = F_BIG;   // leaf
        }
        // argmax(log_softmax(-d)) == first-occurrence argmin(d)
        float best = d0; int bi = 0;
        #pragma unroll
        for (int k = 0; k < 8; k++) { if (d[k] < best) { best = d[k]; bi = k + 1; } }
        float S = __expf(-(d0 - best));
        #pragma unroll
        for (int k = 0; k < 8; k++) S += __expf(-(d[k] - best));  // BIG: exp->0
        float mp = -__logf(S);     // max of log_softmax
        prob += mp;
        if (t == 0) prob += mp;    // source quirk: first iter adds max_prob twice
        if (bi == 0) {
            float4 n2 = g_node2[cur];
            if (n2.z != 0.f) { o0 = prob + n2.x; o1 = prob + n2.y; }
            else             { o0 = prob;        o1 = prob;        }
            break;
        }
        cur = base + bi - 1;
        d0 = best;                 // == pdist(emb[cur], q), bitwise identical
    }
    ((float2*)out)[qi] = make_float2(o0, o1);
}

// ---------------- launch ------------------------------------------------------
extern "C" void kernel_launch(void* const* d_in, const int* in_sizes, int n_in,
                              void* d_out, int out_size) {
    const float* x  = (const float*)d_in[0];
    const float* nd = (const float*)d_in[1];
    const float* nc = (const float*)d_in[2];
    const int*   ch = (const int*)  d_in[3];
    const float* W1 = (const float*)d_in[4];
    const float* b1 = (const float*)d_in[5];
    const float* W2 = (const float*)d_in[6];
    const float* b2 = (const float*)d_in[7];
    const float* W3 = (const float*)d_in[8];
    const float* b3 = (const float*)d_in[9];
    const float* W4 = (const float*)d_in[10];
    const float* b4 = (const float*)d_in[11];

    cudaFuncSetAttribute(mlp_all_kernel,
                         cudaFuncAttributeMaxDynamicSharedMemorySize, SMEM_BYTES);
    cudaFuncSetAttribute(traverse_kernel,
                         cudaFuncAttributeMaxDynamicSharedMemorySize, TRAV_SMEM);

    mlp_all_kernel<<<MLP_GRID, MLP_BLOCK, SMEM_BYTES>>>(x, nd,
                                                        W1, b1, W2, b2,
                                                        W3, b3, W4, b4);
    precompute_kernel<<<MN / 256, 256>>>(nc, ch);
    traverse_kernel<<<TRAV_GRID, TRAV_BLOCK, TRAV_SMEM>>>((float*)d_out);
}

// round 15
// speedup vs baseline: 1.0638x; 1.0638x over previous
#include <cuda_runtime.h>
#include <cstdint>

#define DEVI __device__ __forceinline__

constexpr int NQ = 131072;   // queries
constexpr int MN = 8192;     // tree nodes
constexpr float F_EPS = 1e-6f;
constexpr float F_BIG = 1e9f;

// ---------------- shared-memory layout (float word offsets) ------------------
constexpr int OFF_W1 = 0;        // [2][100]                       (200)
constexpr int OFF_B1 = 200;      // 100 -> 300, pad 304
constexpr int OFF_W2 = 304;      // [100][104] = 10400 -> 10704 (cols 100..103 zero)
constexpr int OFF_B2 = 10704;    // 104 -> 10808
constexpr int OFF_W3 = 10808;    // [100][32] = 3200 -> 14008 (cols 30,31 zero)
constexpr int OFF_B3 = 14008;    // 32 -> 14040
constexpr int OFF_W4 = 14040;    // [32][2] = 64 -> 14104
constexpr int OFF_B4 = 14104;    // 2 pad 8 -> 14112
constexpr int OFF_H  = 14112;    // per-group h block: [k][4 rows]
constexpr int H_GSTRIDE = 404;   // 400 + 4 pad
constexpr int R_ROWS  = 4;       // rows per 8-lane group
constexpr int GROUPS  = 60;      // 8-lane groups per CTA (4 per warp)
constexpr int MLP_BLOCK = 480;   // 15 warps, reg cap 136 (measured 104)
constexpr int MLP_GRID  = 152;
constexpr int SMEM_FLOATS = OFF_H + GROUPS * H_GSTRIDE;   // 38352
constexpr int SMEM_BYTES  = SMEM_FLOATS * 4;              // 153,408 B

constexpr int CHUNKS = (MN + NQ) / R_ROWS;            // 34816 (exact)
constexpr int SLOTS  = MLP_GRID * GROUPS;             // 9120
constexpr int ROUNDS = (CHUNKS + SLOTS - 1) / SLOTS;  // 4 -> 95.4% fill

// traverse kernel: whole g_emb staged in smem; prob2 computed inline at stop
constexpr int TRAV_BLOCK = 1024;
constexpr int TRAV_GRID  = NQ / TRAV_BLOCK;           // 128, one query/thread
constexpr int TRAV_SMEM  = (MN + 8) * 8;              // 65,600 B

// ---------------- scratch (device globals: no allocation allowed) ------------
__device__ float2 g_emb[MN + 8]; // +8 pad (zero-init): node 1023's child loads
__device__ float2 g_qx[NQ];      // transformed queries

typedef unsigned long long u64;

// ---------------- packed fp32x2 helpers (sm_100+ PTX) ------------------------
DEVI u64 pack2(float lo, float hi) {
    u64 r;
    asm("mov.b64 %0, {%1, %2};"
        : "=l"(r) : "r"(__float_as_uint(lo)), "r"(__float_as_uint(hi)));
    return r;
}
DEVI void unpack2(u64 v, float &lo, float &hi) {
    unsigned a, b;
    asm("mov.b64 {%0, %1}, %2;" : "=r"(a), "=r"(b) : "l"(v));
    lo = __uint_as_float(a); hi = __uint_as_float(b);
}
DEVI void fma2(u64 &d, u64 a, u64 b) {
    asm("fma.rn.f32x2 %0, %1, %2, %0;" : "+l"(d) : "l"(a), "l"(b));
}

// torch.nn.PairwiseDistance: ||a - b + eps||_2
DEVI float pdist(float ax, float ay, float bx, float by) {
    float dx = ax - bx + F_EPS;
    float dy = ay - by + F_EPS;
    return sqrtf(fmaf(dx, dx, dy * dy));
}

// ---------------- kernel 1: fused node+query MLP (measured-best body) --------
// Work unit = 4-row chunk per 8-lane group (4 groups/warp). Lane q owns layer-2
// cols {2q+16j, 2q+16j+1 : j=0..5} (LDS.64 pairs) + singleton col 96+q, for
// all 4 rows. h exchanged via the group's SMEM block ([k][4 rows], one LDS.128
// per k). Layer 3: cols {2q,2q+1,2q+16,2q+17}. Layer 4 reduced via shfl.xor.
__global__ void __launch_bounds__(MLP_BLOCK, 1)
mlp_all_kernel(const float* __restrict__ x, const float* __restrict__ nd,
               const float* __restrict__ W1, const float* __restrict__ b1,
               const float* __restrict__ W2, const float* __restrict__ b2,
               const float* __restrict__ W3, const float* __restrict__ b3,
               const float* __restrict__ W4, const float* __restrict__ b4) {
    extern __shared__ float sm[];
    const int t = threadIdx.x;

    // zero weight region (covers all pad slots), then fill
    for (int i = t; i < OFF_H; i += MLP_BLOCK) sm[i] = 0.f;
    __syncthreads();
    for (int i = t; i < 200; i += MLP_BLOCK) sm[OFF_W1 + i] = W1[i];
    for (int i = t; i < 100; i += MLP_BLOCK) sm[OFF_B1 + i] = b1[i];
    for (int i = t; i < 10000; i += MLP_BLOCK) {
        int k = i / 100, j = i - k * 100;
        sm[OFF_W2 + k * 104 + j] = W2[i];
    }
    for (int j = t; j < 100; j += MLP_BLOCK) sm[OFF_B2 + j] = b2[j];
    for (int i = t; i < 3000; i += MLP_BLOCK) {
        int k = i / 30, j = i - k * 30;
        sm[OFF_W3 + k * 32 + j] = W3[i];
    }
    for (int i = t; i < 30; i += MLP_BLOCK) sm[OFF_B3 + i] = b3[i];
    for (int i = t; i < 60; i += MLP_BLOCK) sm[OFF_W4 + i] = W4[i];
    if (t < 2) sm[OFF_B4 + t] = b4[t];
    __syncthreads();

    const int lane = t & 31;
    const int q   = lane & 7;                   // lane within group
    const int gid = (t >> 5) * 4 + (lane >> 3); // group in CTA, 0..59
    float* hg = sm + OFF_H + gid * H_GSTRIDE;

    int chunk = blockIdx.x * GROUPS + gid;

    for (int rnd = 0; rnd < ROUNDS; rnd++, chunk += SLOTS) {
        const bool active = chunk < CHUNKS;
        const int row0 = chunk * R_ROWS;

        // ---- layer 1 (2 -> 100): lane computes h1[kk][0..3], kk = q+8j -----
        if (active) {
            const bool isnode = row0 < MN;   // MN%4==0: chunk never straddles
            const float4* src = (const float4*)(
                (isnode ? nd : x) + (size_t)(isnode ? row0 : row0 - MN) * 2);
            float4 v0 = __ldg(src + 0), v1 = __ldg(src + 1);
            // rows: (v0.x,v0.y) (v0.z,v0.w) (v1.x,v1.y) (v1.z,v1.w)
            float x0[4] = {v0.x, v0.z, v1.x, v1.z};
            float x1[4] = {v0.y, v0.w, v1.y, v1.w};
            #pragma unroll
            for (int j = 0; j < 13; j++) {
                int kk = q + 8 * j;
                if (kk < 100) {
                    float wa = sm[OFF_W1 + kk];
                    float wb = sm[OFF_W1 + 100 + kk];
                    float bb = sm[OFF_B1 + kk];
                    float hv[4];
                    #pragma unroll
                    for (int r = 0; r < 4; r++)
                        hv[r] = fmaxf(fmaf(x0[r], wa, fmaf(x1[r], wb, bb)), 0.f);
                    *(float4*)(hg + kk * 4) = make_float4(hv[0], hv[1], hv[2], hv[3]);
                }
            }
        }
        __syncwarp();

        // ---- layer 2 (100 -> 100): 6 col-pairs + 1 singleton, x 4 rows -----
        u64 acc[6][4];
        float sc[4];
        {
            #pragma unroll
            for (int j = 0; j < 6; j++) {
                u64 bv = *(const u64*)(sm + OFF_B2 + 2 * q + 16 * j);
                #pragma unroll
                for (int r = 0; r < 4; r++) acc[j][r] = bv;
            }
            float bs = sm[OFF_B2 + 96 + q];
            #pragma unroll
            for (int r = 0; r < 4; r++) sc[r] = bs;
        }
        const float* w2q = sm + OFF_W2 + 2 * q;
        const float* w2s = sm + OFF_W2 + 96 + q;
        #pragma unroll 4
        for (int k = 0; k < 100; k++) {
            float4 h4 = *(const float4*)(hg + k * 4);
            float hr[4] = {h4.x, h4.y, h4.z, h4.w};
            u64 hh[4];
            #pragma unroll
            for (int r = 0; r < 4; r++) hh[r] = pack2(hr[r], hr[r]);
            const float* wr = w2q + k * 104;
            #pragma unroll
            for (int j = 0; j < 6; j++) {
                u64 w = *(const u64*)(wr + 16 * j);
                #pragma unroll
                for (int r = 0; r < 4; r++) fma2(acc[j][r], hh[r], w);
            }
            float wsv = w2s[k * 104];
            #pragma unroll
            for (int r = 0; r < 4; r++) sc[r] = fmaf(hr[r], wsv, sc[r]);
        }
        __syncwarp();   // all lanes done reading h1 before overwriting with h2

        // relu + write h2 back to the group's h block
        if (active) {
            #pragma unroll
            for (int j = 0; j < 6; j++) {
                float va[4], vb[4];
                #pragma unroll
                for (int r = 0; r < 4; r++) {
                    float a, b; unpack2(acc[j][r], a, b);
                    va[r] = fmaxf(a, 0.f); vb[r] = fmaxf(b, 0.f);
                }
                int c0 = 2 * q + 16 * j;
                *(float4*)(hg + c0 * 4)       = make_float4(va[0], va[1], va[2], va[3]);
                *(float4*)(hg + (c0 + 1) * 4) = make_float4(vb[0], vb[1], vb[2], vb[3]);
            }
            if (q < 4) {   // singleton cols 96..99
                float vs[4];
                #pragma unroll
                for (int r = 0; r < 4; r++) vs[r] = fmaxf(sc[r], 0.f);
                *(float4*)(hg + (96 + q) * 4) = make_float4(vs[0], vs[1], vs[2], vs[3]);
            }
        }
        __syncwarp();

        // ---- layer 3 (100 -> 30 pad 32): lane cols {2q,2q+1,2q+16,2q+17} ---
        u64 a3[2][4];
        {
            u64 b0 = *(const u64*)(sm + OFF_B3 + 2 * q);
            u64 b1v = *(const u64*)(sm + OFF_B3 + 2 * q + 16);
            #pragma unroll
            for (int r = 0; r < 4; r++) { a3[0][r] = b0; a3[1][r] = b1v; }
        }
        const float* w3q = sm + OFF_W3 + 2 * q;
        #pragma unroll 4
        for (int k = 0; k < 100; k++) {
            float4 h4 = *(const float4*)(hg + k * 4);
            float hr[4] = {h4.x, h4.y, h4.z, h4.w};
            u64 hh[4];
            #pragma unroll
            for (int r = 0; r < 4; r++) hh[r] = pack2(hr[r], hr[r]);
            const float* wr = w3q + k * 32;
            u64 w0 = *(const u64*)(wr);
            u64 w1v = *(const u64*)(wr + 16);
            #pragma unroll
            for (int r = 0; r < 4; r++) {
                fma2(a3[0][r], hh[r], w0);
                fma2(a3[1][r], hh[r], w1v);
            }
        }

        // ---- layer 4 (30 -> 2): partials over this lane's 4 cols -----------
        float o0[4], o1[4];
        #pragma unroll
        for (int r = 0; r < 4; r++) { o0[r] = 0.f; o1[r] = 0.f; }
        #pragma unroll
        for (int jj = 0; jj < 2; jj++) {
            int cA = 2 * q + 16 * jj;
            float2 wA = *(const float2*)(sm + OFF_W4 + 2 * cA);
            float2 wB = *(const float2*)(sm + OFF_W4 + 2 * cA + 2);
            #pragma unroll
            for (int r = 0; r < 4; r++) {
                float a, b; unpack2(a3[jj][r], a, b);
                a = fmaxf(a, 0.f); b = fmaxf(b, 0.f);
                o0[r] = fmaf(a, wA.x, o0[r]);
                o1[r] = fmaf(a, wA.y, o1[r]);
                o0[r] = fmaf(b, wB.x, o0[r]);
                o1[r] = fmaf(b, wB.y, o1[r]);
            }
        }
        // reduce across the 8-lane group (full-warp shfl, all threads join)
        #pragma unroll
        for (int r = 0; r < 4; r++) {
            o0[r] += __shfl_xor_sync(0xffffffffu, o0[r], 1);
            o0[r] += __shfl_xor_sync(0xffffffffu, o0[r], 2);
            o0[r] += __shfl_xor_sync(0xffffffffu, o0[r], 4);
            o1[r] += __shfl_xor_sync(0xffffffffu, o1[r], 1);
            o1[r] += __shfl_xor_sync(0xffffffffu, o1[r], 2);
            o1[r] += __shfl_xor_sync(0xffffffffu, o1[r], 4);
        }
        if (active && q < 4) {
            // lane q emits row q (static selects, no local-mem indexing)
            float s0 = (q == 0) ? o0[0] : (q == 1) ? o0[1] : (q == 2) ? o0[2] : o0[3];
            float s1 = (q == 0) ? o1[0] : (q == 1) ? o1[1] : (q == 2) ? o1[2] : o1[3];
            float2 ov = make_float2(s0 + sm[OFF_B4 + 0], s1 + sm[OFF_B4 + 1]);
            int row = row0 + q;
            if (row < MN) g_emb[row] = ov;
            else          g_qx[row - MN] = ov;
        }
        __syncwarp();
    }
}

// ---------------- kernel 2: traversal + inline prob2 (fused epilogue) --------
// Complete 8-ary tree: children of node i are {8i+1..8i+8} clipped at 8191;
// leaves are i >= 1024. g_emb staged in smem (65.6 KB). At the stop node,
// prob2 (node-to-children softmax class mixture) is computed INLINE from the
// smem embeddings + node_classes (children class rows are 64 contiguous
// bytes) — the separate precompute kernel and g_node2 buffer are gone.
__global__ void __launch_bounds__(TRAV_BLOCK)
traverse_kernel(const float* __restrict__ nc, float* __restrict__ out) {
    extern __shared__ float2 semb[];
    // stage g_emb (MN+8 float2 = 4100 float4, 1024 threads -> ~4 each)
    {
        const float4* srcv = (const float4*)g_emb;
        float4* dstv = (float4*)semb;
        for (int i = threadIdx.x; i < (MN + 8) / 2; i += TRAV_BLOCK)
            dstv[i] = __ldg(srcv + i);
    }
    __syncthreads();

    const int qi = blockIdx.x * TRAV_BLOCK + threadIdx.x;   // covers NQ exactly
    const float2 qx = g_qx[qi];
    const float q0 = qx.x, q1 = qx.y;

    int cur = 0;
    float2 e0 = semb[0];
    float d0 = pdist(e0.x, e0.y, q0, q1);
    float prob = 0.f, o0 = 0.f, o1 = 0.f;

    for (int t = 0; t < 16; t++) {
        const int base = 8 * cur + 1;
        float d[8];
        if (cur < 1024) {
            #pragma unroll
            for (int k = 0; k < 8; k++) {
                float2 ec = semb[base + k];    // padded: base+7 <= 8199 < MN+8
                d[k] = pdist(ec.x, ec.y, q0, q1);
            }
            if (cur == 1023) d[7] = F_BIG;     // node 8192 doesn't exist
        } else {
            #pragma unroll
            for (int k = 0; k < 8; k++) d[k] = F_BIG;   // leaf
        }
        // argmax(log_softmax(-d)) == first-occurrence argmin(d)
        float best = d0; int bi = 0;
        #pragma unroll
        for (int k = 0; k < 8; k++) { if (d[k] < best) { best = d[k]; bi = k + 1; } }
        float S = __expf(-(d0 - best));
        #pragma unroll
        for (int k = 0; k < 8; k++) S += __expf(-(d[k] - best));  // BIG: exp->0
        float mp = -__logf(S);     // max of log_softmax
        prob += mp;
        if (t == 0) prob += mp;    // source quirk: first iter adds max_prob twice
        if (bi == 0) {
            if (cur < 1024) {
                // inline prob2: softmax(-dist(emb[cur], children)) class mix
                float2 ecur = semb[cur];
                float dn[8];
                #pragma unroll
                for (int k = 0; k < 8; k++) {
                    float2 ec = semb[base + k];
                    dn[k] = pdist(ecur.x, ecur.y, ec.x, ec.y);
                }
                if (cur == 1023) dn[7] = F_BIG;
                float mn = dn[0];
                #pragma unroll
                for (int k = 1; k < 8; k++) mn = fminf(mn, dn[k]);
                float Sn = 0.f, m0 = 0.f, m1 = 0.f;
                #pragma unroll
                for (int k = 0; k < 8; k++) {
                    float ek = __expf(-(dn[k] - mn));   // BIG slot -> 0
                    Sn += ek;
                    int cidx = base + k;
                    if (cidx < MN) {                    // guard OOB class load
                        float2 ncv = *(const float2*)(nc + 2 * cidx);
                        m0 = fmaf(ek, ncv.x, m0);
                        m1 = fmaf(ek, ncv.y, m1);
                    }
                }
                m0 /= Sn; m1 /= Sn;
                o0 = prob + __logf(fmaxf(m0, 1e-30f));
                o1 = prob + __logf(fmaxf(m1, 1e-30f));
            } else {
                o0 = prob; o1 = prob;                   // leaf: no children
            }
            break;
        }
        cur = base + bi - 1;
        d0 = best;                 // == pdist(emb[cur], q), bitwise identical
    }
    ((float2*)out)[qi] = make_float2(o0, o1);
}

// ---------------- launch ------------------------------------------------------
extern "C" void kernel_launch(void* const* d_in, const int* in_sizes, int n_in,
                              void* d_out, int out_size) {
    const float* x  = (const float*)d_in[0];
    const float* nd = (const float*)d_in[1];
    const float* nc = (const float*)d_in[2];
    const float* W1 = (const float*)d_in[4];
    const float* b1 = (const float*)d_in[5];
    const float* W2 = (const float*)d_in[6];
    const float* b2 = (const float*)d_in[7];
    const float* W3 = (const float*)d_in[8];
    const float* b3 = (const float*)d_in[9];
    const float* W4 = (const float*)d_in[10];
    const float* b4 = (const float*)d_in[11];

    cudaFuncSetAttribute(mlp_all_kernel,
                         cudaFuncAttributeMaxDynamicSharedMemorySize, SMEM_BYTES);
    cudaFuncSetAttribute(traverse_kernel,
                         cudaFuncAttributeMaxDynamicSharedMemorySize, TRAV_SMEM);

    mlp_all_kernel<<<MLP_GRID, MLP_BLOCK, SMEM_BYTES>>>(x, nd,
                                                        W1, b1, W2, b2,
                                                        W3, b3, W4, b4);
    traverse_kernel<<<TRAV_GRID, TRAV_BLOCK, TRAV_SMEM>>>(nc, (float*)d_out);
}

// round 16
// speedup vs baseline: 1.0642x; 1.0003x over previous
#include <cuda_runtime.h>
#include <cstdint>

#define DEVI __device__ __forceinline__

constexpr int NQ = 131072;   // queries
constexpr int MN = 8192;     // tree nodes
constexpr float F_EPS = 1e-6f;
constexpr float F_BIG = 1e9f;

// ---------------- shared-memory layout (float word offsets) ------------------
constexpr int OFF_W1 = 0;        // [2][100]                       (200)
constexpr int OFF_B1 = 200;      // 100 -> 300, pad 304
constexpr int OFF_W2 = 304;      // [100][104] = 10400 -> 10704 (cols 100..103 zero)
constexpr int OFF_B2 = 10704;    // 104 -> 10808
constexpr int OFF_W3 = 10808;    // [100][32] = 3200 -> 14008 (cols 30,31 zero)
constexpr int OFF_B3 = 14008;    // 32 -> 14040
constexpr int OFF_W4 = 14040;    // [32][2] = 64 -> 14104
constexpr int OFF_B4 = 14104;    // 2 pad 8 -> 14112
constexpr int OFF_H  = 14112;    // per-group h block: [k][4 rows]
constexpr int H_GSTRIDE = 404;   // 400 + 4 pad
constexpr int R_ROWS  = 4;       // rows per 8-lane group
constexpr int GROUPS  = 60;      // 8-lane groups per CTA (4 per warp)
constexpr int MLP_BLOCK = 480;   // 15 warps, reg cap 136 (measured 104)
constexpr int MLP_GRID  = 152;
constexpr int SMEM_FLOATS = OFF_H + GROUPS * H_GSTRIDE;   // 38352
constexpr int SMEM_BYTES  = SMEM_FLOATS * 4;              // 153,408 B

constexpr int CHUNKS = (MN + NQ) / R_ROWS;            // 34816 (exact)
constexpr int SLOTS  = MLP_GRID * GROUPS;             // 9120
constexpr int ROUNDS = (CHUNKS + SLOTS - 1) / SLOTS;  // 4 -> 95.4% fill

// traverse kernel: whole g_emb staged in smem; prob2 computed inline at stop
constexpr int TRAV_BLOCK = 1024;
constexpr int TRAV_GRID  = NQ / TRAV_BLOCK;           // 128, one query/thread
constexpr int TRAV_SMEM  = (MN + 8) * 8;              // 65,600 B

// ---------------- scratch (device globals: no allocation allowed) ------------
__device__ float2 g_emb[MN + 8]; // +8 pad (zero-init): node 1023's child loads
__device__ float2 g_qx[NQ];      // transformed queries

typedef unsigned long long u64;

// ---------------- packed fp32x2 helpers (sm_100+ PTX) ------------------------
DEVI u64 pack2(float lo, float hi) {
    u64 r;
    asm("mov.b64 %0, {%1, %2};"
        : "=l"(r) : "r"(__float_as_uint(lo)), "r"(__float_as_uint(hi)));
    return r;
}
DEVI void unpack2(u64 v, float &lo, float &hi) {
    unsigned a, b;
    asm("mov.b64 {%0, %1}, %2;" : "=r"(a), "=r"(b) : "l"(v));
    lo = __uint_as_float(a); hi = __uint_as_float(b);
}
DEVI void fma2(u64 &d, u64 a, u64 b) {
    asm("fma.rn.f32x2 %0, %1, %2, %0;" : "+l"(d) : "l"(a), "l"(b));
}

// torch.nn.PairwiseDistance: ||a - b + eps||_2
DEVI float pdist(float ax, float ay, float bx, float by) {
    float dx = ax - bx + F_EPS;
    float dy = ay - by + F_EPS;
    return sqrtf(fmaf(dx, dx, dy * dy));
}

// ---------------- kernel 1: fused node+query MLP (measured-best body, FROZEN) 
// Work unit = 4-row chunk per 8-lane group (4 groups/warp). Lane q owns layer-2
// cols {2q+16j, 2q+16j+1 : j=0..5} (LDS.64 pairs) + singleton col 96+q, for
// all 4 rows. h exchanged via the group's SMEM block ([k][4 rows], one LDS.128
// per k). Layer 3: cols {2q,2q+1,2q+16,2q+17}. Layer 4 reduced via shfl.xor.
__global__ void __launch_bounds__(MLP_BLOCK, 1)
mlp_all_kernel(const float* __restrict__ x, const float* __restrict__ nd,
               const float* __restrict__ W1, const float* __restrict__ b1,
               const float* __restrict__ W2, const float* __restrict__ b2,
               const float* __restrict__ W3, const float* __restrict__ b3,
               const float* __restrict__ W4, const float* __restrict__ b4) {
    extern __shared__ float sm[];
    const int t = threadIdx.x;

    // zero weight region (covers all pad slots), then fill
    for (int i = t; i < OFF_H; i += MLP_BLOCK) sm[i] = 0.f;
    __syncthreads();
    for (int i = t; i < 200; i += MLP_BLOCK) sm[OFF_W1 + i] = W1[i];
    for (int i = t; i < 100; i += MLP_BLOCK) sm[OFF_B1 + i] = b1[i];
    for (int i = t; i < 10000; i += MLP_BLOCK) {
        int k = i / 100, j = i - k * 100;
        sm[OFF_W2 + k * 104 + j] = W2[i];
    }
    for (int j = t; j < 100; j += MLP_BLOCK) sm[OFF_B2 + j] = b2[j];
    for (int i = t; i < 3000; i += MLP_BLOCK) {
        int k = i / 30, j = i - k * 30;
        sm[OFF_W3 + k * 32 + j] = W3[i];
    }
    for (int i = t; i < 30; i += MLP_BLOCK) sm[OFF_B3 + i] = b3[i];
    for (int i = t; i < 60; i += MLP_BLOCK) sm[OFF_W4 + i] = W4[i];
    if (t < 2) sm[OFF_B4 + t] = b4[t];
    __syncthreads();

    const int lane = t & 31;
    const int q   = lane & 7;                   // lane within group
    const int gid = (t >> 5) * 4 + (lane >> 3); // group in CTA, 0..59
    float* hg = sm + OFF_H + gid * H_GSTRIDE;

    int chunk = blockIdx.x * GROUPS + gid;

    for (int rnd = 0; rnd < ROUNDS; rnd++, chunk += SLOTS) {
        const bool active = chunk < CHUNKS;
        const int row0 = chunk * R_ROWS;

        // ---- layer 1 (2 -> 100): lane computes h1[kk][0..3], kk = q+8j -----
        if (active) {
            const bool isnode = row0 < MN;   // MN%4==0: chunk never straddles
            const float4* src = (const float4*)(
                (isnode ? nd : x) + (size_t)(isnode ? row0 : row0 - MN) * 2);
            float4 v0 = __ldg(src + 0), v1 = __ldg(src + 1);
            // rows: (v0.x,v0.y) (v0.z,v0.w) (v1.x,v1.y) (v1.z,v1.w)
            float x0[4] = {v0.x, v0.z, v1.x, v1.z};
            float x1[4] = {v0.y, v0.w, v1.y, v1.w};
            #pragma unroll
            for (int j = 0; j < 13; j++) {
                int kk = q + 8 * j;
                if (kk < 100) {
                    float wa = sm[OFF_W1 + kk];
                    float wb = sm[OFF_W1 + 100 + kk];
                    float bb = sm[OFF_B1 + kk];
                    float hv[4];
                    #pragma unroll
                    for (int r = 0; r < 4; r++)
                        hv[r] = fmaxf(fmaf(x0[r], wa, fmaf(x1[r], wb, bb)), 0.f);
                    *(float4*)(hg + kk * 4) = make_float4(hv[0], hv[1], hv[2], hv[3]);
                }
            }
        }
        __syncwarp();

        // ---- layer 2 (100 -> 100): 6 col-pairs + 1 singleton, x 4 rows -----
        u64 acc[6][4];
        float sc[4];
        {
            #pragma unroll
            for (int j = 0; j < 6; j++) {
                u64 bv = *(const u64*)(sm + OFF_B2 + 2 * q + 16 * j);
                #pragma unroll
                for (int r = 0; r < 4; r++) acc[j][r] = bv;
            }
            float bs = sm[OFF_B2 + 96 + q];
            #pragma unroll
            for (int r = 0; r < 4; r++) sc[r] = bs;
        }
        const float* w2q = sm + OFF_W2 + 2 * q;
        const float* w2s = sm + OFF_W2 + 96 + q;
        #pragma unroll 4
        for (int k = 0; k < 100; k++) {
            float4 h4 = *(const float4*)(hg + k * 4);
            float hr[4] = {h4.x, h4.y, h4.z, h4.w};
            u64 hh[4];
            #pragma unroll
            for (int r = 0; r < 4; r++) hh[r] = pack2(hr[r], hr[r]);
            const float* wr = w2q + k * 104;
            #pragma unroll
            for (int j = 0; j < 6; j++) {
                u64 w = *(const u64*)(wr + 16 * j);
                #pragma unroll
                for (int r = 0; r < 4; r++) fma2(acc[j][r], hh[r], w);
            }
            float wsv = w2s[k * 104];
            #pragma unroll
            for (int r = 0; r < 4; r++) sc[r] = fmaf(hr[r], wsv, sc[r]);
        }
        __syncwarp();   // all lanes done reading h1 before overwriting with h2

        // relu + write h2 back to the group's h block
        if (active) {
            #pragma unroll
            for (int j = 0; j < 6; j++) {
                float va[4], vb[4];
                #pragma unroll
                for (int r = 0; r < 4; r++) {
                    float a, b; unpack2(acc[j][r], a, b);
                    va[r] = fmaxf(a, 0.f); vb[r] = fmaxf(b, 0.f);
                }
                int c0 = 2 * q + 16 * j;
                *(float4*)(hg + c0 * 4)       = make_float4(va[0], va[1], va[2], va[3]);
                *(float4*)(hg + (c0 + 1) * 4) = make_float4(vb[0], vb[1], vb[2], vb[3]);
            }
            if (q < 4) {   // singleton cols 96..99
                float vs[4];
                #pragma unroll
                for (int r = 0; r < 4; r++) vs[r] = fmaxf(sc[r], 0.f);
                *(float4*)(hg + (96 + q) * 4) = make_float4(vs[0], vs[1], vs[2], vs[3]);
            }
        }
        __syncwarp();

        // ---- layer 3 (100 -> 30 pad 32): lane cols {2q,2q+1,2q+16,2q+17} ---
        u64 a3[2][4];
        {
            u64 b0 = *(const u64*)(sm + OFF_B3 + 2 * q);
            u64 b1v = *(const u64*)(sm + OFF_B3 + 2 * q + 16);
            #pragma unroll
            for (int r = 0; r < 4; r++) { a3[0][r] = b0; a3[1][r] = b1v; }
        }
        const float* w3q = sm + OFF_W3 + 2 * q;
        #pragma unroll 4
        for (int k = 0; k < 100; k++) {
            float4 h4 = *(const float4*)(hg + k * 4);
            float hr[4] = {h4.x, h4.y, h4.z, h4.w};
            u64 hh[4];
            #pragma unroll
            for (int r = 0; r < 4; r++) hh[r] = pack2(hr[r], hr[r]);
            const float* wr = w3q + k * 32;
            u64 w0 = *(const u64*)(wr);
            u64 w1v = *(const u64*)(wr + 16);
            #pragma unroll
            for (int r = 0; r < 4; r++) {
                fma2(a3[0][r], hh[r], w0);
                fma2(a3[1][r], hh[r], w1v);
            }
        }

        // ---- layer 4 (30 -> 2): partials over this lane's 4 cols -----------
        float o0[4], o1[4];
        #pragma unroll
        for (int r = 0; r < 4; r++) { o0[r] = 0.f; o1[r] = 0.f; }
        #pragma unroll
        for (int jj = 0; jj < 2; jj++) {
            int cA = 2 * q + 16 * jj;
            float2 wA = *(const float2*)(sm + OFF_W4 + 2 * cA);
            float2 wB = *(const float2*)(sm + OFF_W4 + 2 * cA + 2);
            #pragma unroll
            for (int r = 0; r < 4; r++) {
                float a, b; unpack2(a3[jj][r], a, b);
                a = fmaxf(a, 0.f); b = fmaxf(b, 0.f);
                o0[r] = fmaf(a, wA.x, o0[r]);
                o1[r] = fmaf(a, wA.y, o1[r]);
                o0[r] = fmaf(b, wB.x, o0[r]);
                o1[r] = fmaf(b, wB.y, o1[r]);
            }
        }
        // reduce across the 8-lane group (full-warp shfl, all threads join)
        #pragma unroll
        for (int r = 0; r < 4; r++) {
            o0[r] += __shfl_xor_sync(0xffffffffu, o0[r], 1);
            o0[r] += __shfl_xor_sync(0xffffffffu, o0[r], 2);
            o0[r] += __shfl_xor_sync(0xffffffffu, o0[r], 4);
            o1[r] += __shfl_xor_sync(0xffffffffu, o1[r], 1);
            o1[r] += __shfl_xor_sync(0xffffffffu, o1[r], 2);
            o1[r] += __shfl_xor_sync(0xffffffffu, o1[r], 4);
        }
        if (active && q < 4) {
            // lane q emits row q (static selects, no local-mem indexing)
            float s0 = (q == 0) ? o0[0] : (q == 1) ? o0[1] : (q == 2) ? o0[2] : o0[3];
            float s1 = (q == 0) ? o1[0] : (q == 1) ? o1[1] : (q == 2) ? o1[2] : o1[3];
            float2 ov = make_float2(s0 + sm[OFF_B4 + 0], s1 + sm[OFF_B4 + 1]);
            int row = row0 + q;
            if (row < MN) g_emb[row] = ov;
            else          g_qx[row - MN] = ov;
        }
        __syncwarp();
    }
}

// ---------------- kernel 2: traversal + inline prob2 + LEAF EARLY-EXIT -------
// Complete 8-ary tree: children of node i are {8i+1..8i+8} clipped at 8191;
// leaves are i >= 1024. g_emb staged in smem (65.6 KB).
//
// Leaf identity (bitwise): at a leaf all child dists are BIG -> best = d0,
// bi = 0, S = exp(0) + 8*exp(-(BIG-d0)) = 1 exactly (underflow), mp = 0, and
// out = prob_new = prob (no children). So the final softmax step is a no-op;
// exit immediately. This removes one full step (19 MUFU + 8 LDS + ~50 issues)
// for every leaf-terminating query and shortens the divergent warp tail.
__global__ void __launch_bounds__(TRAV_BLOCK)
traverse_kernel(const float* __restrict__ nc, float* __restrict__ out) {
    extern __shared__ float2 semb[];
    // stage g_emb (MN+8 float2 = 4100 float4, 1024 threads -> ~4 each)
    {
        const float4* srcv = (const float4*)g_emb;
        float4* dstv = (float4*)semb;
        for (int i = threadIdx.x; i < (MN + 8) / 2; i += TRAV_BLOCK)
            dstv[i] = __ldg(srcv + i);
    }
    __syncthreads();

    const int qi = blockIdx.x * TRAV_BLOCK + threadIdx.x;   // covers NQ exactly
    const float2 qx = g_qx[qi];
    const float q0 = qx.x, q1 = qx.y;

    int cur = 0;
    float2 e0 = semb[0];
    float d0 = pdist(e0.x, e0.y, q0, q1);
    float prob = 0.f, o0 = 0.f, o1 = 0.f;

    for (int t = 0; t < 16; t++) {
        if (cur >= 1024) {                     // LEAF: provably mp=0, out=prob
            o0 = prob; o1 = prob;
            break;
        }
        const int base = 8 * cur + 1;
        float d[8];
        #pragma unroll
        for (int k = 0; k < 8; k++) {
            float2 ec = semb[base + k];        // padded: base+7 <= 8199 < MN+8
            d[k] = pdist(ec.x, ec.y, q0, q1);
        }
        if (cur == 1023) d[7] = F_BIG;         // node 8192 doesn't exist
        // argmax(log_softmax(-d)) == first-occurrence argmin(d)
        float best = d0; int bi = 0;
        #pragma unroll
        for (int k = 0; k < 8; k++) { if (d[k] < best) { best = d[k]; bi = k + 1; } }
        float S = __expf(-(d0 - best));
        #pragma unroll
        for (int k = 0; k < 8; k++) S += __expf(-(d[k] - best));  // BIG: exp->0
        float mp = -__logf(S);     // max of log_softmax
        prob += mp;
        if (t == 0) prob += mp;    // source quirk: first iter adds max_prob twice
        if (bi == 0) {
            // inline prob2: softmax(-dist(emb[cur], children)) class mixture
            float2 ecur = semb[cur];
            float dn[8];
            #pragma unroll
            for (int k = 0; k < 8; k++) {
                float2 ec = semb[base + k];
                dn[k] = pdist(ecur.x, ecur.y, ec.x, ec.y);
            }
            if (cur == 1023) dn[7] = F_BIG;
            float mn = dn[0];
            #pragma unroll
            for (int k = 1; k < 8; k++) mn = fminf(mn, dn[k]);
            float Sn = 0.f, m0 = 0.f, m1 = 0.f;
            #pragma unroll
            for (int k = 0; k < 8; k++) {
                float ek = __expf(-(dn[k] - mn));   // BIG slot -> 0
                Sn += ek;
                int cidx = base + k;
                if (cidx < MN) {                    // guard OOB class load
                    float2 ncv = *(const float2*)(nc + 2 * cidx);
                    m0 = fmaf(ek, ncv.x, m0);
                    m1 = fmaf(ek, ncv.y, m1);
                }
            }
            m0 /= Sn; m1 /= Sn;
            o0 = prob + __logf(fmaxf(m0, 1e-30f));
            o1 = prob + __logf(fmaxf(m1, 1e-30f));
            break;
        }
        cur = base + bi - 1;
        d0 = best;                 // == pdist(emb[cur], q), bitwise identical
    }
    ((float2*)out)[qi] = make_float2(o0, o1);
}

// ---------------- launch ------------------------------------------------------
extern "C" void kernel_launch(void* const* d_in, const int* in_sizes, int n_in,
                              void* d_out, int out_size) {
    const float* x  = (const float*)d_in[0];
    const float* nd = (const float*)d_in[1];
    const float* nc = (const float*)d_in[2];
    const float* W1 = (const float*)d_in[4];
    const float* b1 = (const float*)d_in[5];
    const float* W2 = (const float*)d_in[6];
    const float* b2 = (const float*)d_in[7];
    const float* W3 = (const float*)d_in[8];
    const float* b3 = (const float*)d_in[9];
    const float* W4 = (const float*)d_in[10];
    const float* b4 = (const float*)d_in[11];

    cudaFuncSetAttribute(mlp_all_kernel,
                         cudaFuncAttributeMaxDynamicSharedMemorySize, SMEM_BYTES);
    cudaFuncSetAttribute(traverse_kernel,
                         cudaFuncAttributeMaxDynamicSharedMemorySize, TRAV_SMEM);

    mlp_all_kernel<<<MLP_GRID, MLP_BLOCK, SMEM_BYTES>>>(x, nd,
                                                        W1, b1, W2, b2,
                                                        W3, b3, W4, b4);
    traverse_kernel<<<TRAV_GRID, TRAV_BLOCK, TRAV_SMEM>>>(nc, (float*)d_out);
}